// round 6
// baseline (speedup 1.0000x reference)
#include <cuda_runtime.h>
#include <cstdint>

#define T_STEPS 1024
#define B_SZ    64
#define H_SZ    512
#define IN_SZ   512
#define G4      2048
#define NCTA    128
#define NGRP    4          // independent batch groups
#define CPG     32         // CTAs per group
#define BPG     16         // batches per group
#define UPC     16         // hidden units per CTA

#define WS2 68             // ws[k][64 rows], pad 68 (=4*17): ks lanes -> disjoint banks
#define HS2 16             // hs[k][16 b], contiguous: 2-phase h loads, 16B-aligned

// ---------------- scratch ----------------
__device__ float    g_xpT[(size_t)T_STEPS * G4 * B_SZ];            // [t][g][b]
__device__ float    g_hT [(size_t)T_STEPS * NGRP * H_SZ * BPG];    // [t][grp][j][b]
__device__ unsigned g_arrive[NCTA];                                // barrier flags

// ---------------- helpers ----------------
__device__ __forceinline__ float sigf(float x) { return 1.0f / (1.0f + __expf(-x)); }
__device__ __forceinline__ float tanh_fast(float x) {
    float ax = fabsf(x);
    float e  = __expf(-2.0f * ax);
    float t  = (1.0f - e) / (1.0f + e);
    return copysignf(t, x);
}
__device__ __forceinline__ unsigned smem_u32(const void* p) {
    return (unsigned)__cvta_generic_to_shared(p);
}
__device__ __forceinline__ void cp_async16(unsigned dst, const void* src) {
    asm volatile("cp.async.ca.shared.global [%0], [%1], 16;" :: "r"(dst), "l"(src));
}
__device__ __forceinline__ void cp_commit() {
    asm volatile("cp.async.commit_group;" ::: "memory");
}
__device__ __forceinline__ void cp_wait0() {
    asm volatile("cp.async.wait_group 0;" ::: "memory");
}
__device__ __forceinline__ void lds_v4(float& a, float& b, float& c, float& d, unsigned addr) {
    asm volatile("ld.shared.v4.f32 {%0, %1, %2, %3}, [%4];"
                 : "=f"(a), "=f"(b), "=f"(c), "=f"(d) : "r"(addr));
}
__device__ __forceinline__ void lds_v2(float& a, float& b, unsigned addr) {
    asm volatile("ld.shared.v2.f32 {%0, %1}, [%2];" : "=f"(a), "=f"(b) : "r"(addr));
}
__device__ __forceinline__ void sts_f32(unsigned addr, float a) {
    asm volatile("st.shared.f32 [%0], %1;" :: "r"(addr), "f"(a));
}

// Group barrier: 32 CTAs of one batch group. st.release publishes prior
// global writes (h); monotonic generation across graph replays.
__device__ __forceinline__ void group_barrier(int ct, int gbase, int tid, unsigned target) {
    __syncthreads();
    if (tid == 0) {
        asm volatile("st.release.gpu.global.u32 [%0], %1;"
                     :: "l"(&g_arrive[ct]), "r"(target) : "memory");
    }
    if (tid < CPG) {
        unsigned v;
        do {
            asm volatile("ld.acquire.gpu.global.u32 %0, [%1];"
                         : "=r"(v) : "l"(&g_arrive[gbase + tid]) : "memory");
        } while ((int)(v - target) < 0);
    }
    __syncthreads();
}

// =====================================================================
// Phase 1: xpT[t][g][b] = x @ Wx^T + (bx + bh).  (R1 scalar version, 5.0 ms)
// =====================================================================
__global__ __launch_bounds__(256) void xp_gemm(
    const float* __restrict__ x,
    const float* __restrict__ Wx0, const float* __restrict__ Wx1,
    const float* __restrict__ Wx2, const float* __restrict__ Wx3,
    const float* __restrict__ bx0, const float* __restrict__ bx1,
    const float* __restrict__ bx2, const float* __restrict__ bx3,
    const float* __restrict__ bh0, const float* __restrict__ bh1,
    const float* __restrict__ bh2, const float* __restrict__ bh3)
{
    const int BM = 128, BN = 64, BK = 16;
    __shared__ __align__(16) float As[BK][BM];
    __shared__ __align__(16) float Bs[BK][BN];

    const int bxi = blockIdx.x;
    const int byi = blockIdx.y;
    const int tid = threadIdx.x;

    const int gate = bxi >> 3;
    const int gin0 = (bxi & 7) * BN;
    const float* W   = (gate == 0) ? Wx0 : (gate == 1) ? Wx1 : (gate == 2) ? Wx2 : Wx3;
    const float* bxp = (gate == 0) ? bx0 : (gate == 1) ? bx1 : (gate == 2) ? bx2 : bx3;
    const float* bhp = (gate == 0) ? bh0 : (gate == 1) ? bh1 : (gate == 2) ? bh2 : bh3;

    const int row0 = byi * BM;
    const int tm   = tid & 15;
    const int tn   = tid >> 4;

    float acc[8][4];
    #pragma unroll
    for (int i = 0; i < 8; i++)
        #pragma unroll
        for (int j = 0; j < 4; j++) acc[i][j] = 0.0f;

    for (int kk = 0; kk < IN_SZ; kk += BK) {
        #pragma unroll
        for (int it = 0; it < 2; it++) {
            int idx = tid + it * 256;
            int m = idx >> 2, k4 = idx & 3;
            float4 a = *(const float4*)&x[(size_t)(row0 + m) * IN_SZ + kk + k4 * 4];
            As[k4 * 4 + 0][m] = a.x; As[k4 * 4 + 1][m] = a.y;
            As[k4 * 4 + 2][m] = a.z; As[k4 * 4 + 3][m] = a.w;
        }
        {
            int n = tid >> 2, k4 = tid & 3;
            float4 b = *(const float4*)&W[(size_t)(gin0 + n) * IN_SZ + kk + k4 * 4];
            Bs[k4 * 4 + 0][n] = b.x; Bs[k4 * 4 + 1][n] = b.y;
            Bs[k4 * 4 + 2][n] = b.z; Bs[k4 * 4 + 3][n] = b.w;
        }
        __syncthreads();

        #pragma unroll
        for (int k = 0; k < BK; k++) {
            float4 a0 = *(const float4*)&As[k][tm * 8];
            float4 a1 = *(const float4*)&As[k][tm * 8 + 4];
            float4 bv = *(const float4*)&Bs[k][tn * 4];
            float am[8] = {a0.x, a0.y, a0.z, a0.w, a1.x, a1.y, a1.z, a1.w};
            float bb[4] = {bv.x, bv.y, bv.z, bv.w};
            #pragma unroll
            for (int i = 0; i < 8; i++)
                #pragma unroll
                for (int j = 0; j < 4; j++)
                    acc[i][j] = fmaf(am[i], bb[j], acc[i][j]);
        }
        __syncthreads();
    }

    float bias[4];
    int   gcol[4];
    #pragma unroll
    for (int j = 0; j < 4; j++) {
        int gl = gin0 + tn * 4 + j;
        gcol[j] = gate * 512 + gl;
        bias[j] = bxp[gl] + bhp[gl];
    }
    #pragma unroll
    for (int i = 0; i < 8; i++) {
        int M0 = row0 + tm * 8 + i;
        size_t t0 = (size_t)(M0 >> 6);
        int b0 = M0 & 63;
        #pragma unroll
        for (int j = 0; j < 4; j++) {
            g_xpT[(t0 * G4 + gcol[j]) * B_SZ + b0] = acc[i][j] + bias[j];
        }
    }
}

// =====================================================================
// Phase 2: persistent recurrence. 4 groups x 32 CTAs, 1 CTA/SM.
// CTA: 64 gate-rows (16 units x 4 gates) x 16 batches, K=512.
// Thread tile: 8 rows x 2 batches x k-split-4. Scalar FFMA, pipelined LDS.
// fp32 floor: 4096 FFMA/thread -> 8192 cyc/step per SMSP.
// =====================================================================
__global__ __launch_bounds__(256, 1) void lstm_rec(
    const float* __restrict__ Whf, const float* __restrict__ Whi,
    const float* __restrict__ Who, const float* __restrict__ Whg,
    float* __restrict__ out)
{
    extern __shared__ float sm[];
    float* ws  = sm;                        // [512][68]  136 KB
    float* hs  = ws + 512 * WS2;            // [512][16]  32 KB
    float* zbT = hs + 512 * HS2;            // [16][65]   4.1 KB
    __shared__ unsigned s_base;

    const int ct  = blockIdx.x;
    const int tid = threadIdx.x;
    const int g   = ct >> 5;
    const int cw  = ct & 31;
    const int gb  = g << 5;
    const int j0  = cw * UPC;
    const int B0  = g * BPG;

    // Load Wh slice transposed: ws[k*68 + r], r = q*16 + ul
    for (int idx = tid; idx < 64 * 512; idx += 256) {
        int r = idx >> 9;
        int k = idx & 511;
        int q = r >> 4, ul = r & 15;
        const float* whp = (q == 0) ? Whf : (q == 1) ? Whi : (q == 2) ? Who : Whg;
        ws[k * WS2 + r] = whp[(size_t)(j0 + ul) * H_SZ + k];
    }
    if (tid == 0) s_base = g_arrive[ct];
    __syncthreads();
    const unsigned base = s_base;

    const int ks = tid & 3;             // k-slice: k = 4*kk + ks
    const int bg = (tid >> 2) & 7;      // batch pair
    const int rg = tid >> 5;            // row octet (= warp id)
    const int b0 = 2 * bg;
    const int r0 = 8 * rg;

    const unsigned ws_u = smem_u32(ws);
    const unsigned hs_u = smem_u32(hs);
    const unsigned zb_u = smem_u32(zbT);
    const unsigned wa0  = ws_u + (unsigned)((ks * WS2 + r0) * 4);
    const unsigned ha0  = hs_u + (unsigned)((ks * HS2 + b0) * 4);
    const unsigned WSTP = 4 * WS2 * 4;   // byte stride per kk
    const unsigned HSTP = 4 * HS2 * 4;

    const int uul = tid >> 4;           // unit 0..15
    const int uub = tid & 15;           // batch 0..15
    float c_reg = 0.0f;

    for (int t = 0; t < T_STEPS; t++) {
        // xp prefetch (gmem, independent of h; consumed at gate update)
        float xq0, xq1, xq2, xq3;
        {
            size_t xb = ((size_t)t * G4 + j0 + uul) * B_SZ + B0 + uub;
            xq0 = g_xpT[xb];
            xq1 = g_xpT[xb + (size_t)512 * B_SZ];
            xq2 = g_xpT[xb + (size_t)1024 * B_SZ];
            xq3 = g_xpT[xb + (size_t)1536 * B_SZ];
        }

        float acc[8][2];
        #pragma unroll
        for (int i = 0; i < 8; i++) { acc[i][0] = 0.f; acc[i][1] = 0.f; }

        if (t > 0) {
            // stage group h_{t-1}: 32 KB = 2048 x 16B, 8 per thread
            const float* hsrc = g_hT + (((size_t)(t - 1) * NGRP + g) * H_SZ) * BPG;
            #pragma unroll
            for (int i = 0; i < 8; i++) {
                int idx = tid + i * 256;
                int k = idx >> 2, b4 = idx & 3;
                cp_async16(hs_u + (unsigned)((k * HS2 + b4 * 4) * 4),
                           hsrc + (size_t)k * BPG + b4 * 4);
            }
            cp_commit();
            cp_wait0();
            __syncthreads();

            // software-pipelined: load kk+1 before FMAs of kk
            float w0[8], w1[8], ha[2], hb[2];
            lds_v4(w0[0], w0[1], w0[2], w0[3], wa0);
            lds_v4(w0[4], w0[5], w0[6], w0[7], wa0 + 16);
            lds_v2(ha[0], ha[1], ha0);

            #pragma unroll 4
            for (int kk = 0; kk < 127; kk++) {
                unsigned wa = wa0 + (unsigned)(kk + 1) * WSTP;
                unsigned hh = ha0 + (unsigned)(kk + 1) * HSTP;
                lds_v4(w1[0], w1[1], w1[2], w1[3], wa);
                lds_v4(w1[4], w1[5], w1[6], w1[7], wa + 16);
                lds_v2(hb[0], hb[1], hh);
                #pragma unroll
                for (int i = 0; i < 8; i++) {
                    acc[i][0] = fmaf(w0[i], ha[0], acc[i][0]);
                    acc[i][1] = fmaf(w0[i], ha[1], acc[i][1]);
                }
                #pragma unroll
                for (int i = 0; i < 8; i++) w0[i] = w1[i];
                ha[0] = hb[0]; ha[1] = hb[1];
            }
            #pragma unroll
            for (int i = 0; i < 8; i++) {
                acc[i][0] = fmaf(w0[i], ha[0], acc[i][0]);
                acc[i][1] = fmaf(w0[i], ha[1], acc[i][1]);
            }
        }

        // reduce across 4 k-slices (lane bits 0-1)
        #pragma unroll
        for (int i = 0; i < 8; i++) {
            #pragma unroll
            for (int j = 0; j < 2; j++) {
                float v = acc[i][j];
                v += __shfl_xor_sync(0xffffffffu, v, 1);
                v += __shfl_xor_sync(0xffffffffu, v, 2);
                acc[i][j] = v;
            }
        }
        if (ks == 0) {
            #pragma unroll
            for (int i = 0; i < 8; i++) {
                sts_f32(zb_u + (unsigned)((b0 * 65 + r0 + i) * 4),       acc[i][0]);
                sts_f32(zb_u + (unsigned)(((b0 + 1) * 65 + r0 + i) * 4), acc[i][1]);
            }
        }
        __syncthreads();

        // gate update: rows f=ul, i=16+ul, o=32+ul, g=48+ul at batch uub
        {
            float zf = zbT[uub * 65 + 0  + uul] + xq0;
            float zi = zbT[uub * 65 + 16 + uul] + xq1;
            float zo = zbT[uub * 65 + 32 + uul] + xq2;
            float zg = zbT[uub * 65 + 48 + uul] + xq3;
            float f  = sigf(zf);
            float ii = sigf(zi);
            float o  = sigf(zo);
            float gg = tanh_fast(zg);
            c_reg    = fmaf(f, c_reg, ii * gg);
            float h  = o * tanh_fast(c_reg);
            int j = j0 + uul;
            int B = B0 + uub;
            out[((size_t)t * B_SZ + B) * H_SZ + j] = h;
            g_hT[(((size_t)t * NGRP + g) * H_SZ + j) * BPG + uub] = h;
            if (t == T_STEPS - 1) {
                size_t tail = (size_t)T_STEPS * B_SZ * H_SZ;
                out[tail + (size_t)B * H_SZ + j] = h;
                out[tail + (size_t)B_SZ * H_SZ + (size_t)B * H_SZ + j] = c_reg;
            }
        }

        group_barrier(ct, gb, tid, base + (unsigned)t + 1u);
    }
}

// =====================================================================
extern "C" void kernel_launch(void* const* d_in, const int* in_sizes, int n_in,
                              void* d_out, int out_size)
{
    const float* x   = (const float*)d_in[0];
    const float* Wxf = (const float*)d_in[1];  const float* bxf = (const float*)d_in[2];
    const float* Whf = (const float*)d_in[3];  const float* bhf = (const float*)d_in[4];
    const float* Wxi = (const float*)d_in[5];  const float* bxi = (const float*)d_in[6];
    const float* Whi = (const float*)d_in[7];  const float* bhi = (const float*)d_in[8];
    const float* Wxo = (const float*)d_in[9];  const float* bxo = (const float*)d_in[10];
    const float* Who = (const float*)d_in[11]; const float* bho = (const float*)d_in[12];
    const float* Wxg = (const float*)d_in[13]; const float* bxg = (const float*)d_in[14];
    const float* Whg = (const float*)d_in[15]; const float* bhg = (const float*)d_in[16];
    float* out = (float*)d_out;

    dim3 ggrid(G4 / 64, (T_STEPS * B_SZ) / 128);
    xp_gemm<<<ggrid, 256>>>(x, Wxf, Wxi, Wxo, Wxg,
                            bxf, bxi, bxo, bxg,
                            bhf, bhi, bho, bhg);

    const int smem_bytes = (512 * WS2 + 512 * HS2 + 16 * 65) * 4;
    cudaFuncSetAttribute(lstm_rec, cudaFuncAttributeMaxDynamicSharedMemorySize, smem_bytes);
    lstm_rec<<<NCTA, 256, smem_bytes>>>(Whf, Whi, Who, Whg, out);
}

// round 7
// speedup vs baseline: 1.0953x; 1.0953x over previous
#include <cuda_runtime.h>
#include <cstdint>

#define T_STEPS 1024
#define B_SZ    64
#define H_SZ    512
#define IN_SZ   512
#define G4      2048
#define NCTA    128
#define NSTR    8          // independent batch streams
#define CPS     32         // CTAs per stream
#define BPS     8          // batches per stream
#define UPC     16         // hidden units per CTA (64 gate-rows)

#define WS2 68             // ws[k][64 rows] pad: 8 k-slices -> disjoint bank quads
#define HS2 12             // hs[k][8 b] pad: 32 lanes -> 32 distinct banks

// ---------------- scratch ----------------
__device__ float    g_xpT[(size_t)T_STEPS * G4 * B_SZ];            // [t][g][b]
__device__ float    g_hT [(size_t)T_STEPS * NSTR * H_SZ * BPS];    // [t][s][j][b]
__device__ unsigned g_arrive[NSTR * CPS];                          // per-stream flags

// ---------------- helpers ----------------
__device__ __forceinline__ float tanh_apx(float x) {
    float y;
    asm("tanh.approx.f32 %0, %1;" : "=f"(y) : "f"(x));
    return y;
}
__device__ __forceinline__ float sig_apx(float x) {
    return fmaf(0.5f, tanh_apx(0.5f * x), 0.5f);
}
__device__ __forceinline__ unsigned smem_u32(const void* p) {
    return (unsigned)__cvta_generic_to_shared(p);
}
__device__ __forceinline__ void cp_async16(unsigned dst, const void* src) {
    asm volatile("cp.async.ca.shared.global [%0], [%1], 16;" :: "r"(dst), "l"(src));
}
__device__ __forceinline__ void cp_commit_wait() {
    asm volatile("cp.async.commit_group;\ncp.async.wait_group 0;" ::: "memory");
}
__device__ __forceinline__ void lds_v4(float& a, float& b, float& c, float& d, unsigned addr) {
    asm volatile("ld.shared.v4.f32 {%0, %1, %2, %3}, [%4];"
                 : "=f"(a), "=f"(b), "=f"(c), "=f"(d) : "r"(addr));
}
__device__ __forceinline__ void lds_f32(float& a, unsigned addr) {
    asm volatile("ld.shared.f32 %0, [%1];" : "=f"(a) : "r"(addr));
}
__device__ __forceinline__ void sts_f32(unsigned addr, float a) {
    asm volatile("st.shared.f32 [%0], %1;" :: "r"(addr), "f"(a));
}
__device__ __forceinline__ void flag_release(unsigned* p, unsigned v) {
    asm volatile("st.release.gpu.global.u32 [%0], %1;" :: "l"(p), "r"(v) : "memory");
}
__device__ __forceinline__ unsigned flag_acquire(const unsigned* p) {
    unsigned v;
    asm volatile("ld.acquire.gpu.global.u32 %0, [%1];" : "=r"(v) : "l"(p) : "memory");
    return v;
}

// =====================================================================
// Phase 1: xpT[t][g][b] = x @ Wx^T + (bx + bh).  (known-good scalar GEMM)
// =====================================================================
__global__ __launch_bounds__(256) void xp_gemm(
    const float* __restrict__ x,
    const float* __restrict__ Wx0, const float* __restrict__ Wx1,
    const float* __restrict__ Wx2, const float* __restrict__ Wx3,
    const float* __restrict__ bx0, const float* __restrict__ bx1,
    const float* __restrict__ bx2, const float* __restrict__ bx3,
    const float* __restrict__ bh0, const float* __restrict__ bh1,
    const float* __restrict__ bh2, const float* __restrict__ bh3)
{
    const int BM = 128, BN = 64, BK = 16;
    __shared__ __align__(16) float As[BK][BM];
    __shared__ __align__(16) float Bs[BK][BN];

    const int bxi = blockIdx.x;
    const int byi = blockIdx.y;
    const int tid = threadIdx.x;

    const int gate = bxi >> 3;
    const int gin0 = (bxi & 7) * BN;
    const float* W   = (gate == 0) ? Wx0 : (gate == 1) ? Wx1 : (gate == 2) ? Wx2 : Wx3;
    const float* bxp = (gate == 0) ? bx0 : (gate == 1) ? bx1 : (gate == 2) ? bx2 : bx3;
    const float* bhp = (gate == 0) ? bh0 : (gate == 1) ? bh1 : (gate == 2) ? bh2 : bh3;

    const int row0 = byi * BM;
    const int tm   = tid & 15;
    const int tn   = tid >> 4;

    float acc[8][4];
    #pragma unroll
    for (int i = 0; i < 8; i++)
        #pragma unroll
        for (int j = 0; j < 4; j++) acc[i][j] = 0.0f;

    for (int kk = 0; kk < IN_SZ; kk += BK) {
        #pragma unroll
        for (int it = 0; it < 2; it++) {
            int idx = tid + it * 256;
            int m = idx >> 2, k4 = idx & 3;
            float4 a = *(const float4*)&x[(size_t)(row0 + m) * IN_SZ + kk + k4 * 4];
            As[k4 * 4 + 0][m] = a.x; As[k4 * 4 + 1][m] = a.y;
            As[k4 * 4 + 2][m] = a.z; As[k4 * 4 + 3][m] = a.w;
        }
        {
            int n = tid >> 2, k4 = tid & 3;
            float4 b = *(const float4*)&W[(size_t)(gin0 + n) * IN_SZ + kk + k4 * 4];
            Bs[k4 * 4 + 0][n] = b.x; Bs[k4 * 4 + 1][n] = b.y;
            Bs[k4 * 4 + 2][n] = b.z; Bs[k4 * 4 + 3][n] = b.w;
        }
        __syncthreads();

        #pragma unroll
        for (int k = 0; k < BK; k++) {
            float4 a0 = *(const float4*)&As[k][tm * 8];
            float4 a1 = *(const float4*)&As[k][tm * 8 + 4];
            float4 bv = *(const float4*)&Bs[k][tn * 4];
            float am[8] = {a0.x, a0.y, a0.z, a0.w, a1.x, a1.y, a1.z, a1.w};
            float bb[4] = {bv.x, bv.y, bv.z, bv.w};
            #pragma unroll
            for (int i = 0; i < 8; i++)
                #pragma unroll
                for (int j = 0; j < 4; j++)
                    acc[i][j] = fmaf(am[i], bb[j], acc[i][j]);
        }
        __syncthreads();
    }

    float bias[4];
    int   gcol[4];
    #pragma unroll
    for (int j = 0; j < 4; j++) {
        int gl = gin0 + tn * 4 + j;
        gcol[j] = gate * 512 + gl;
        bias[j] = bxp[gl] + bhp[gl];
    }
    #pragma unroll
    for (int i = 0; i < 8; i++) {
        int M0 = row0 + tm * 8 + i;
        size_t t0 = (size_t)(M0 >> 6);
        int b0 = M0 & 63;
        #pragma unroll
        for (int j = 0; j < 4; j++) {
            g_xpT[(t0 * G4 + gcol[j]) * B_SZ + b0] = acc[i][j] + bias[j];
        }
    }
}

// =====================================================================
// Phase 2: persistent recurrence, 2 interleaved batch streams per CTA.
// 8 streams x 8 batches; CTA ct serves streams sA=2*(ct>>5), sB=sA+1 with
// the SAME 16 units (shared Wh slice). While one stream's publish/poll
// latency elapses, the other stream computes.
// 512 threads: k-split 8 x 8 batches x 8 row-octets.
// =====================================================================
__global__ __launch_bounds__(512, 1) void lstm_rec(
    const float* __restrict__ Whf, const float* __restrict__ Whi,
    const float* __restrict__ Who, const float* __restrict__ Whg,
    float* __restrict__ out)
{
    extern __shared__ float sm[];
    float* ws  = sm;                         // [512][68]  136 KB (shared by streams)
    float* hsA = ws  + 512 * WS2;            // [512][12]  24 KB
    float* hsB = hsA + 512 * HS2;            // [512][12]  24 KB
    float* zsA = hsB + 512 * HS2;            // [8][65]
    float* zsB = zsA + 8 * 65;               // [8][65]

    const int ct  = threadIdx.y == 0 ? blockIdx.x : blockIdx.x; // (keep simple)
    const int tid = threadIdx.x;
    const int cw  = ct & 31;                 // CTA within stream set
    const int sA  = (ct >> 5) * 2;
    const int sB  = sA + 1;
    const int j0  = cw * UPC;
    const int B0A = sA * BPS;
    const int B0B = sB * BPS;

    // Load shared Wh slice transposed: ws[k*68 + r], r = q*16 + ul
    for (int idx = tid; idx < 64 * 512; idx += 512) {
        int r = idx >> 9;
        int k = idx & 511;
        int q = r >> 4, ul = r & 15;
        const float* whp = (q == 0) ? Whf : (q == 1) ? Whi : (q == 2) ? Who : Whg;
        ws[k * WS2 + r] = whp[(size_t)(j0 + ul) * H_SZ + k];
    }
    // zero z scratch (used as-is at t=0)
    for (int idx = tid; idx < 2 * 8 * 65; idx += 512) zsA[idx] = 0.0f;

    const unsigned baseA = flag_acquire(&g_arrive[sA * CPS + cw]);
    const unsigned baseB = flag_acquire(&g_arrive[sB * CPS + cw]);
    __syncthreads();

    // compute mapping
    const int ks = tid & 7;                  // k-slice: k = 8*kk + ks
    const int bp = (tid >> 3) & 7;           // batch
    const int rg = tid >> 6;                 // row octet: rows 8*rg..8*rg+7

    const unsigned ws_u  = smem_u32(ws);
    const unsigned hsA_u = smem_u32(hsA);
    const unsigned hsB_u = smem_u32(hsB);
    const unsigned zsA_u = smem_u32(zsA);
    const unsigned zsB_u = smem_u32(zsB);
    const unsigned wa0   = ws_u + (unsigned)((ks * WS2 + 8 * rg) * 4);
    const unsigned WSTP  = 8 * WS2 * 4;
    const unsigned HSTP  = 8 * HS2 * 4;

    // gate-update mapping (threads 0..127)
    const int ul = tid >> 3;
    const int ub = tid & 7;
    float cA = 0.0f, cB = 0.0f;

    for (int t = 0; t < T_STEPS; t++) {
        // prefetch xp for both streams (independent of h)
        float xqA[4], xqB[4];
        if (tid < 128) {
            size_t xb = ((size_t)t * G4 + j0 + ul) * B_SZ;
            #pragma unroll
            for (int q = 0; q < 4; q++) {
                xqA[q] = g_xpT[xb + (size_t)q * 512 * B_SZ + B0A + ub];
                xqB[q] = g_xpT[xb + (size_t)q * 512 * B_SZ + B0B + ub];
            }
        }

        #pragma unroll
        for (int half = 0; half < 2; half++) {
            const int      s    = half ? sB : sA;
            const unsigned hs_u = half ? hsB_u : hsA_u;
            const unsigned zs_u = half ? zsB_u : zsA_u;
            const float*   zs   = half ? zsB : zsA;
            const unsigned base = half ? baseB : baseA;
            const int      B0   = half ? B0B : B0A;
            float&         c    = half ? cB : cA;
            const float*   xq   = half ? xqB : xqA;

            float acc[8];
            #pragma unroll
            for (int i = 0; i < 8; i++) acc[i] = 0.0f;

            if (t > 0) {
                // wait for this stream's producers (usually pre-arrived)
                if (tid < CPS) {
                    const unsigned* fp = &g_arrive[s * CPS + tid];
                    unsigned target = base + (unsigned)t;
                    while ((int)(flag_acquire(fp) - target) < 0) { }
                }
                __syncthreads();

                // stage h_{t-1}: 16 KB = 1024 x 16B, 2 per thread
                const float* hsrc = g_hT + (((size_t)(t - 1) * NSTR + s) * H_SZ) * BPS;
                #pragma unroll
                for (int i = 0; i < 2; i++) {
                    int idx = tid + i * 512;
                    int k = idx >> 1, b4 = idx & 1;
                    cp_async16(hs_u + (unsigned)((k * HS2 + b4 * 4) * 4),
                               hsrc + (size_t)k * BPS + b4 * 4);
                }
                cp_commit_wait();
                __syncthreads();

                // GEMV slice: 8 rows x 1 batch x 64 kk
                const unsigned ha0 = hs_u + (unsigned)((ks * HS2 + bp) * 4);
                #pragma unroll 4
                for (int kk = 0; kk < 64; kk++) {
                    float w[8], hv;
                    unsigned wa = wa0 + (unsigned)kk * WSTP;
                    lds_v4(w[0], w[1], w[2], w[3], wa);
                    lds_v4(w[4], w[5], w[6], w[7], wa + 16);
                    lds_f32(hv, ha0 + (unsigned)kk * HSTP);
                    #pragma unroll
                    for (int i = 0; i < 8; i++)
                        acc[i] = fmaf(w[i], hv, acc[i]);
                }

                // reduce across 8 k-slices (lane bits 0-2)
                #pragma unroll
                for (int i = 0; i < 8; i++) {
                    float v = acc[i];
                    v += __shfl_xor_sync(0xffffffffu, v, 1);
                    v += __shfl_xor_sync(0xffffffffu, v, 2);
                    v += __shfl_xor_sync(0xffffffffu, v, 4);
                    acc[i] = v;
                }
                if (ks == 0) {
                    #pragma unroll
                    for (int i = 0; i < 8; i++)
                        sts_f32(zs_u + (unsigned)((bp * 65 + 8 * rg + i) * 4), acc[i]);
                }
                __syncthreads();
            }

            // gate update: rows f=ul, i=16+ul, o=32+ul, g=48+ul at batch ub
            if (tid < 128) {
                float zf = zs[ub * 65 + 0  + ul] + xq[0];
                float zi = zs[ub * 65 + 16 + ul] + xq[1];
                float zo = zs[ub * 65 + 32 + ul] + xq[2];
                float zg = zs[ub * 65 + 48 + ul] + xq[3];
                float f  = sig_apx(zf);
                float ii = sig_apx(zi);
                float o  = sig_apx(zo);
                float gg = tanh_apx(zg);
                c        = fmaf(f, c, ii * gg);
                float h  = o * tanh_apx(c);
                int j = j0 + ul;
                int B = B0 + ub;
                out[((size_t)t * B_SZ + B) * H_SZ + j] = h;
                g_hT[(((size_t)t * NSTR + s) * H_SZ + j) * BPS + ub] = h;
                if (t == T_STEPS - 1) {
                    size_t tail = (size_t)T_STEPS * B_SZ * H_SZ;
                    out[tail + (size_t)B * H_SZ + j] = h;
                    out[tail + (size_t)B_SZ * H_SZ + (size_t)B * H_SZ + j] = c;
                }
            }
            __syncthreads();
            if (tid == 0)
                flag_release(&g_arrive[s * CPS + cw], base + (unsigned)t + 1u);
        }
    }
}

// =====================================================================
extern "C" void kernel_launch(void* const* d_in, const int* in_sizes, int n_in,
                              void* d_out, int out_size)
{
    const float* x   = (const float*)d_in[0];
    const float* Wxf = (const float*)d_in[1];  const float* bxf = (const float*)d_in[2];
    const float* Whf = (const float*)d_in[3];  const float* bhf = (const float*)d_in[4];
    const float* Wxi = (const float*)d_in[5];  const float* bxi = (const float*)d_in[6];
    const float* Whi = (const float*)d_in[7];  const float* bhi = (const float*)d_in[8];
    const float* Wxo = (const float*)d_in[9];  const float* bxo = (const float*)d_in[10];
    const float* Who = (const float*)d_in[11]; const float* bho = (const float*)d_in[12];
    const float* Wxg = (const float*)d_in[13]; const float* bxg = (const float*)d_in[14];
    const float* Whg = (const float*)d_in[15]; const float* bhg = (const float*)d_in[16];
    float* out = (float*)d_out;

    dim3 ggrid(G4 / 64, (T_STEPS * B_SZ) / 128);
    xp_gemm<<<ggrid, 256>>>(x, Wxf, Wxi, Wxo, Wxg,
                            bxf, bxi, bxo, bxg,
                            bhf, bhi, bho, bhg);

    const int smem_bytes = (512 * WS2 + 2 * 512 * HS2 + 2 * 8 * 65) * 4;
    cudaFuncSetAttribute(lstm_rec, cudaFuncAttributeMaxDynamicSharedMemorySize, smem_bytes);
    lstm_rec<<<NCTA, 512, smem_bytes>>>(Whf, Whi, Who, Whg, out);
}

// round 8
// speedup vs baseline: 2.1391x; 1.9530x over previous
#include <cuda_runtime.h>
#include <cuda_bf16.h>
#include <cstdint>

#define T_STEPS 1024
#define B_SZ    64
#define H_SZ    512
#define IN_SZ   512
#define G4      2048
#define NCTA    128
#define NSTR    8          // independent batch streams
#define CPS     32         // CTAs per stream
#define BPS     8          // batches per stream
#define UPC     16         // hidden units per CTA (64 gate-rows)
#define HSP     520        // padded hs row length (bf16 elems): g*1040B -> distinct bank quads

// ---------------- scratch ----------------
__device__ float          g_xpT[(size_t)T_STEPS * G4 * B_SZ];             // [t][g][b]
__device__ unsigned short g_hhi[(size_t)T_STEPS * NSTR * BPS * H_SZ];     // bf16 hi plane
__device__ unsigned short g_hlo[(size_t)T_STEPS * NSTR * BPS * H_SZ];     // bf16 lo plane
__device__ unsigned       g_arrive[NSTR * CPS];                           // stream flags

// ---------------- helpers ----------------
__device__ __forceinline__ float tanh_apx(float x) {
    float y; asm("tanh.approx.f32 %0, %1;" : "=f"(y) : "f"(x)); return y;
}
__device__ __forceinline__ float sig_apx(float x) {
    return fmaf(0.5f, tanh_apx(0.5f * x), 0.5f);
}
__device__ __forceinline__ unsigned smem_u32(const void* p) {
    return (unsigned)__cvta_generic_to_shared(p);
}
__device__ __forceinline__ void cp_async16(unsigned dst, const void* src) {
    asm volatile("cp.async.ca.shared.global [%0], [%1], 16;" :: "r"(dst), "l"(src));
}
__device__ __forceinline__ void cp_commit_wait() {
    asm volatile("cp.async.commit_group;\ncp.async.wait_group 0;" ::: "memory");
}
__device__ __forceinline__ void flag_release(unsigned* p, unsigned v) {
    asm volatile("st.release.gpu.global.u32 [%0], %1;" :: "l"(p), "r"(v) : "memory");
}
__device__ __forceinline__ unsigned flag_acquire(const unsigned* p) {
    unsigned v;
    asm volatile("ld.acquire.gpu.global.u32 %0, [%1];" : "=r"(v) : "l"(p) : "memory");
    return v;
}
// split fp32 pair into packed bf16 hi/lo (.x -> low 16 bits = lower k index)
__device__ __forceinline__ void split2(float2 v, unsigned& hi, unsigned& lo) {
    unsigned short hx = __bfloat16_as_ushort(__float2bfloat16(v.x));
    unsigned short hy = __bfloat16_as_ushort(__float2bfloat16(v.y));
    float rx = v.x - __bfloat162float(__ushort_as_bfloat16(hx));
    float ry = v.y - __bfloat162float(__ushort_as_bfloat16(hy));
    unsigned short lx = __bfloat16_as_ushort(__float2bfloat16(rx));
    unsigned short ly = __bfloat16_as_ushort(__float2bfloat16(ry));
    hi = (unsigned)hx | ((unsigned)hy << 16);
    lo = (unsigned)lx | ((unsigned)ly << 16);
}
__device__ __forceinline__ void mma16816(float* d, const unsigned* a,
                                         unsigned b0, unsigned b1) {
    asm volatile(
        "mma.sync.aligned.m16n8k16.row.col.f32.bf16.bf16.f32 "
        "{%0,%1,%2,%3}, {%4,%5,%6,%7}, {%8,%9}, {%0,%1,%2,%3};"
        : "+f"(d[0]), "+f"(d[1]), "+f"(d[2]), "+f"(d[3])
        : "r"(a[0]), "r"(a[1]), "r"(a[2]), "r"(a[3]), "r"(b0), "r"(b1));
}

// =====================================================================
// Phase 1: xpT[t][g][b] = x @ Wx^T + (bx + bh).  (known-good scalar GEMM)
// =====================================================================
__global__ __launch_bounds__(256) void xp_gemm(
    const float* __restrict__ x,
    const float* __restrict__ Wx0, const float* __restrict__ Wx1,
    const float* __restrict__ Wx2, const float* __restrict__ Wx3,
    const float* __restrict__ bx0, const float* __restrict__ bx1,
    const float* __restrict__ bx2, const float* __restrict__ bx3,
    const float* __restrict__ bh0, const float* __restrict__ bh1,
    const float* __restrict__ bh2, const float* __restrict__ bh3)
{
    const int BM = 128, BN = 64, BK = 16;
    __shared__ __align__(16) float As[BK][BM];
    __shared__ __align__(16) float Bs[BK][BN];

    const int bxi = blockIdx.x;
    const int byi = blockIdx.y;
    const int tid = threadIdx.x;

    const int gate = bxi >> 3;
    const int gin0 = (bxi & 7) * BN;
    const float* W   = (gate == 0) ? Wx0 : (gate == 1) ? Wx1 : (gate == 2) ? Wx2 : Wx3;
    const float* bxp = (gate == 0) ? bx0 : (gate == 1) ? bx1 : (gate == 2) ? bx2 : bx3;
    const float* bhp = (gate == 0) ? bh0 : (gate == 1) ? bh1 : (gate == 2) ? bh2 : bh3;

    const int row0 = byi * BM;
    const int tm   = tid & 15;
    const int tn   = tid >> 4;

    float acc[8][4];
    #pragma unroll
    for (int i = 0; i < 8; i++)
        #pragma unroll
        for (int j = 0; j < 4; j++) acc[i][j] = 0.0f;

    for (int kk = 0; kk < IN_SZ; kk += BK) {
        #pragma unroll
        for (int it = 0; it < 2; it++) {
            int idx = tid + it * 256;
            int m = idx >> 2, k4 = idx & 3;
            float4 a = *(const float4*)&x[(size_t)(row0 + m) * IN_SZ + kk + k4 * 4];
            As[k4 * 4 + 0][m] = a.x; As[k4 * 4 + 1][m] = a.y;
            As[k4 * 4 + 2][m] = a.z; As[k4 * 4 + 3][m] = a.w;
        }
        {
            int n = tid >> 2, k4 = tid & 3;
            float4 b = *(const float4*)&W[(size_t)(gin0 + n) * IN_SZ + kk + k4 * 4];
            Bs[k4 * 4 + 0][n] = b.x; Bs[k4 * 4 + 1][n] = b.y;
            Bs[k4 * 4 + 2][n] = b.z; Bs[k4 * 4 + 3][n] = b.w;
        }
        __syncthreads();

        #pragma unroll
        for (int k = 0; k < BK; k++) {
            float4 a0 = *(const float4*)&As[k][tm * 8];
            float4 a1 = *(const float4*)&As[k][tm * 8 + 4];
            float4 bv = *(const float4*)&Bs[k][tn * 4];
            float am[8] = {a0.x, a0.y, a0.z, a0.w, a1.x, a1.y, a1.z, a1.w};
            float bb[4] = {bv.x, bv.y, bv.z, bv.w};
            #pragma unroll
            for (int i = 0; i < 8; i++)
                #pragma unroll
                for (int j = 0; j < 4; j++)
                    acc[i][j] = fmaf(am[i], bb[j], acc[i][j]);
        }
        __syncthreads();
    }

    float bias[4];
    int   gcol[4];
    #pragma unroll
    for (int j = 0; j < 4; j++) {
        int gl = gin0 + tn * 4 + j;
        gcol[j] = gate * 512 + gl;
        bias[j] = bxp[gl] + bhp[gl];
    }
    #pragma unroll
    for (int i = 0; i < 8; i++) {
        int M0 = row0 + tm * 8 + i;
        size_t t0 = (size_t)(M0 >> 6);
        int b0 = M0 & 63;
        #pragma unroll
        for (int j = 0; j < 4; j++) {
            g_xpT[(t0 * G4 + gcol[j]) * B_SZ + b0] = acc[i][j] + bias[j];
        }
    }
}

// =====================================================================
// Phase 2: persistent recurrence, tensor-core (HMMA) inner product.
// 8 streams x 32 CTAs; CTA serves streams sA,sB with the SAME 16 units.
// Weights register-stationary as split-bf16 mma A-fragments.
// 16 warps = 4 m-tiles (gates) x 4 k-slices (128 k each).
// =====================================================================
__global__ __launch_bounds__(512, 1) void lstm_rec(
    const float* __restrict__ Whf, const float* __restrict__ Whi,
    const float* __restrict__ Who, const float* __restrict__ Whg,
    float* __restrict__ out)
{
    __shared__ unsigned short hsA[2][BPS * HSP];   // [hi/lo][b*HSP + k]
    __shared__ unsigned short hsB[2][BPS * HSP];
    __shared__ float zpart[4][64][8];              // [kw][row][batch]

    const int tid = threadIdx.x;
    const int ct  = blockIdx.x;
    const int cw  = ct & 31;
    const int sA  = (ct >> 5) * 2;
    const int sB  = sA + 1;
    const int j0  = cw * UPC;
    const int B0A = sA * BPS;
    const int B0B = sB * BPS;

    const int w   = tid >> 5;          // warp 0..15
    const int mt  = w & 3;             // m-tile == gate
    const int kw  = w >> 2;            // k-slice (128 k)
    const int ln  = tid & 31;
    const int g   = ln >> 2;           // row-in-tile g / g+8 ; B batch index
    const int t2  = ln & 3;            // k pair selector

    // ---- register-stationary A fragments (split bf16), all 1024 steps ----
    const float* whp = (mt == 0) ? Whf : (mt == 1) ? Whi : (mt == 2) ? Who : Whg;
    unsigned a_hi[8][4], a_lo[8][4];
    {
        const float* Wr  = whp + (size_t)(j0 + g) * H_SZ;
        const float* Wr8 = whp + (size_t)(j0 + g + 8) * H_SZ;
        #pragma unroll
        for (int kt = 0; kt < 8; kt++) {
            int kb = kw * 128 + kt * 16 + 2 * t2;
            split2(*(const float2*)&Wr [kb],     a_hi[kt][0], a_lo[kt][0]);
            split2(*(const float2*)&Wr8[kb],     a_hi[kt][1], a_lo[kt][1]);
            split2(*(const float2*)&Wr [kb + 8], a_hi[kt][2], a_lo[kt][2]);
            split2(*(const float2*)&Wr8[kb + 8], a_hi[kt][3], a_lo[kt][3]);
        }
    }

    const unsigned baseA = flag_acquire(&g_arrive[sA * CPS + cw]);
    const unsigned baseB = flag_acquire(&g_arrive[sB * CPS + cw]);
    __syncthreads();

    // gate-update mapping (threads 0..127)
    const int ul = tid >> 3;
    const int ub = tid & 7;
    float cA = 0.0f, cB = 0.0f;

    for (int t = 0; t < T_STEPS; t++) {
        // prefetch xp for both streams
        float xqA[4], xqB[4];
        if (tid < 128) {
            size_t xb = ((size_t)t * G4 + j0 + ul) * B_SZ;
            #pragma unroll
            for (int q = 0; q < 4; q++) {
                xqA[q] = g_xpT[xb + (size_t)q * 512 * B_SZ + B0A + ub];
                xqB[q] = g_xpT[xb + (size_t)q * 512 * B_SZ + B0B + ub];
            }
        }

        #pragma unroll
        for (int half = 0; half < 2; half++) {
            const int       s    = half ? sB : sA;
            unsigned short (*hs)[BPS * HSP] = half ? hsB : hsA;
            const unsigned  base = half ? baseB : baseA;
            const int       B0   = half ? B0B : B0A;
            float&          c    = half ? cB : cA;
            const float*    xq   = half ? xqB : xqA;

            if (t > 0) {
                // wait for this stream's producers
                if (tid < CPS) {
                    const unsigned* fp = &g_arrive[s * CPS + tid];
                    unsigned target = base + (unsigned)t;
                    while ((int)(flag_acquire(fp) - target) < 0) { }
                }
                __syncthreads();

                // stage h hi/lo planes: 2 x 8KB, 1024 x 16B chunks
                {
                    const size_t srcb = (((size_t)(t - 1) * NSTR + s) * BPS) * H_SZ;
                    const unsigned d_hi = smem_u32(&hs[0][0]);
                    const unsigned d_lo = smem_u32(&hs[1][0]);
                    #pragma unroll
                    for (int i = 0; i < 2; i++) {
                        int idx = tid + i * 512;            // 0..1023
                        int pl = idx >> 9;                  // plane
                        int b  = (idx >> 6) & 7;
                        int c8 = idx & 63;                  // 8-elem chunk
                        unsigned dst = (pl ? d_lo : d_hi) + (unsigned)(b * HSP + c8 * 8) * 2;
                        const unsigned short* src = (pl ? g_hlo : g_hhi)
                                                    + srcb + (size_t)b * H_SZ + c8 * 8;
                        cp_async16(dst, src);
                    }
                }
                cp_commit_wait();
                __syncthreads();

                // ---- MMA: 8 k-tiles x 3 products ----
                float d[4] = {0.f, 0.f, 0.f, 0.f};
                const unsigned short* hrow_hi = &hs[0][g * HSP];
                const unsigned short* hrow_lo = &hs[1][g * HSP];
                #pragma unroll
                for (int kt = 0; kt < 8; kt++) {
                    int kb = kw * 128 + kt * 16 + 2 * t2;
                    unsigned bh0 = *(const unsigned*)&hrow_hi[kb];
                    unsigned bh1 = *(const unsigned*)&hrow_hi[kb + 8];
                    unsigned bl0 = *(const unsigned*)&hrow_lo[kb];
                    unsigned bl1 = *(const unsigned*)&hrow_lo[kb + 8];
                    mma16816(d, a_hi[kt], bh0, bh1);   // hi * h_hi
                    mma16816(d, a_lo[kt], bh0, bh1);   // lo * h_hi
                    mma16816(d, a_hi[kt], bl0, bl1);   // hi * h_lo
                }

                // ---- store partials: rows 16*mt+g / +8, cols 2t,2t+1 ----
                *(float2*)&zpart[kw][16 * mt + g][2 * t2]     = make_float2(d[0], d[1]);
                *(float2*)&zpart[kw][16 * mt + g + 8][2 * t2] = make_float2(d[2], d[3]);
            }
            __syncthreads();

            // ---- gate update (threads 0..127): unit ul, batch ub ----
            if (tid < 128) {
                float z[4];
                #pragma unroll
                for (int q = 0; q < 4; q++) {
                    float v = xq[q];
                    if (t > 0) {
                        #pragma unroll
                        for (int k4 = 0; k4 < 4; k4++)
                            v += zpart[k4][16 * q + ul][ub];
                    }
                    z[q] = v;
                }
                float f  = sig_apx(z[0]);
                float ii = sig_apx(z[1]);
                float o  = sig_apx(z[2]);
                float gg = tanh_apx(z[3]);
                c        = fmaf(f, c, ii * gg);
                float h  = o * tanh_apx(c);
                int j = j0 + ul;
                int B = B0 + ub;
                out[((size_t)t * B_SZ + B) * H_SZ + j] = h;
                // publish split-bf16 h
                unsigned short hh = __bfloat16_as_ushort(__float2bfloat16(h));
                float rr = h - __bfloat162float(__ushort_as_bfloat16(hh));
                unsigned short hl = __bfloat16_as_ushort(__float2bfloat16(rr));
                size_t hb = (((size_t)t * NSTR + s) * BPS + ub) * H_SZ + j;
                g_hhi[hb] = hh;
                g_hlo[hb] = hl;
                if (t == T_STEPS - 1) {
                    size_t tail = (size_t)T_STEPS * B_SZ * H_SZ;
                    out[tail + (size_t)B * H_SZ + j] = h;
                    out[tail + (size_t)B_SZ * H_SZ + (size_t)B * H_SZ + j] = c;
                }
            }
            __syncthreads();
            if (tid == 0)
                flag_release(&g_arrive[s * CPS + cw], base + (unsigned)t + 1u);
        }
    }
}

// =====================================================================
extern "C" void kernel_launch(void* const* d_in, const int* in_sizes, int n_in,
                              void* d_out, int out_size)
{
    const float* x   = (const float*)d_in[0];
    const float* Wxf = (const float*)d_in[1];  const float* bxf = (const float*)d_in[2];
    const float* Whf = (const float*)d_in[3];  const float* bhf = (const float*)d_in[4];
    const float* Wxi = (const float*)d_in[5];  const float* bxi = (const float*)d_in[6];
    const float* Whi = (const float*)d_in[7];  const float* bhi = (const float*)d_in[8];
    const float* Wxo = (const float*)d_in[9];  const float* bxo = (const float*)d_in[10];
    const float* Who = (const float*)d_in[11]; const float* bho = (const float*)d_in[12];
    const float* Wxg = (const float*)d_in[13]; const float* bxg = (const float*)d_in[14];
    const float* Whg = (const float*)d_in[15]; const float* bhg = (const float*)d_in[16];
    float* out = (float*)d_out;

    dim3 ggrid(G4 / 64, (T_STEPS * B_SZ) / 128);
    xp_gemm<<<ggrid, 256>>>(x, Wxf, Wxi, Wxo, Wxg,
                            bxf, bxi, bxo, bxg,
                            bhf, bhi, bho, bhg);

    lstm_rec<<<NCTA, 512>>>(Whf, Whi, Who, Whg, out);
}

// round 9
// speedup vs baseline: 3.5102x; 1.6410x over previous
#include <cuda_runtime.h>
#include <cuda_bf16.h>
#include <cstdint>

#define T_STEPS 1024
#define B_SZ    64
#define H_SZ    512
#define IN_SZ   512
#define G4      2048
#define NCTA    128
#define NSTR    8          // independent batch streams
#define CPS     32         // CTAs per stream
#define BPS     8          // batches per stream
#define UPC     16         // hidden units per CTA (64 gate-rows)
#define HSP     520        // padded hs row length (bf16) in lstm_rec

#define MROWS   65536      // T*B
#define BKS     24         // xp_mma smem row stride in ushorts (48 B, conflict-free)

// ---------------- scratch ----------------
__device__ float          g_xpT[(size_t)T_STEPS * G4 * B_SZ];             // [t][g][b]
__device__ unsigned short g_hhi[(size_t)T_STEPS * NSTR * BPS * H_SZ];     // h bf16 hi
__device__ unsigned short g_hlo[(size_t)T_STEPS * NSTR * BPS * H_SZ];     // h bf16 lo
__device__ unsigned       g_arrive[NSTR * CPS];                           // stream flags
__device__ unsigned short g_xhi[(size_t)MROWS * IN_SZ];                   // x bf16 hi
__device__ unsigned short g_xlo[(size_t)MROWS * IN_SZ];                   // x bf16 lo
__device__ unsigned short g_whi[(size_t)G4 * IN_SZ];                      // Wx bf16 hi
__device__ unsigned short g_wlo[(size_t)G4 * IN_SZ];                      // Wx bf16 lo
__device__ float          g_bias[G4];                                     // bx + bh

// ---------------- helpers ----------------
__device__ __forceinline__ float tanh_apx(float x) {
    float y; asm("tanh.approx.f32 %0, %1;" : "=f"(y) : "f"(x)); return y;
}
__device__ __forceinline__ float sig_apx(float x) {
    return fmaf(0.5f, tanh_apx(0.5f * x), 0.5f);
}
__device__ __forceinline__ unsigned smem_u32(const void* p) {
    return (unsigned)__cvta_generic_to_shared(p);
}
__device__ __forceinline__ void cp_async16(unsigned dst, const void* src) {
    asm volatile("cp.async.ca.shared.global [%0], [%1], 16;" :: "r"(dst), "l"(src));
}
__device__ __forceinline__ void cp_commit() {
    asm volatile("cp.async.commit_group;" ::: "memory");
}
__device__ __forceinline__ void cp_wait_n(int n) {
    if (n == 0) asm volatile("cp.async.wait_group 0;" ::: "memory");
    else        asm volatile("cp.async.wait_group 1;" ::: "memory");
}
__device__ __forceinline__ void cp_commit_wait() {
    asm volatile("cp.async.commit_group;\ncp.async.wait_group 0;" ::: "memory");
}
__device__ __forceinline__ void flag_release(unsigned* p, unsigned v) {
    asm volatile("st.release.gpu.global.u32 [%0], %1;" :: "l"(p), "r"(v) : "memory");
}
__device__ __forceinline__ unsigned flag_acquire(const unsigned* p) {
    unsigned v;
    asm volatile("ld.acquire.gpu.global.u32 %0, [%1];" : "=r"(v) : "l"(p) : "memory");
    return v;
}
__device__ __forceinline__ void split1(float v, unsigned short& hi, unsigned short& lo) {
    hi = __bfloat16_as_ushort(__float2bfloat16(v));
    float r = v - __bfloat162float(__ushort_as_bfloat16(hi));
    lo = __bfloat16_as_ushort(__float2bfloat16(r));
}
__device__ __forceinline__ void split2(float2 v, unsigned& hi, unsigned& lo) {
    unsigned short hx, lx, hy, ly;
    split1(v.x, hx, lx); split1(v.y, hy, ly);
    hi = (unsigned)hx | ((unsigned)hy << 16);
    lo = (unsigned)lx | ((unsigned)ly << 16);
}
__device__ __forceinline__ void mma16816(float* d, const unsigned* a,
                                         unsigned b0, unsigned b1) {
    asm volatile(
        "mma.sync.aligned.m16n8k16.row.col.f32.bf16.bf16.f32 "
        "{%0,%1,%2,%3}, {%4,%5,%6,%7}, {%8,%9}, {%0,%1,%2,%3};"
        : "+f"(d[0]), "+f"(d[1]), "+f"(d[2]), "+f"(d[3])
        : "r"(a[0]), "r"(a[1]), "r"(a[2]), "r"(a[3]), "r"(b0), "r"(b1));
}

// =====================================================================
// Converters: split fp32 -> bf16 hi/lo planes
// =====================================================================
__global__ __launch_bounds__(256) void convert_x(const float* __restrict__ x) {
    size_t i = ((size_t)blockIdx.x * 256 + threadIdx.x) * 4;
    float4 v = *(const float4*)&x[i];
    unsigned short h[4], l[4];
    split1(v.x, h[0], l[0]); split1(v.y, h[1], l[1]);
    split1(v.z, h[2], l[2]); split1(v.w, h[3], l[3]);
    *(ushort4*)&g_xhi[i] = make_ushort4(h[0], h[1], h[2], h[3]);
    *(ushort4*)&g_xlo[i] = make_ushort4(l[0], l[1], l[2], l[3]);
}

__global__ __launch_bounds__(128) void convert_w(
    const float* __restrict__ Wx0, const float* __restrict__ Wx1,
    const float* __restrict__ Wx2, const float* __restrict__ Wx3,
    const float* __restrict__ bx0, const float* __restrict__ bx1,
    const float* __restrict__ bx2, const float* __restrict__ bx3,
    const float* __restrict__ bh0, const float* __restrict__ bh1,
    const float* __restrict__ bh2, const float* __restrict__ bh3)
{
    int gidx = blockIdx.x;                 // 0..2047
    int gate = gidx >> 9, r = gidx & 511;
    const float* W = (gate == 0) ? Wx0 : (gate == 1) ? Wx1 : (gate == 2) ? Wx2 : Wx3;
    size_t base = (size_t)gidx * IN_SZ;
    for (int k = threadIdx.x * 4; k < IN_SZ; k += 128 * 4) {
        float4 v = *(const float4*)&W[(size_t)r * IN_SZ + k];
        unsigned short h[4], l[4];
        split1(v.x, h[0], l[0]); split1(v.y, h[1], l[1]);
        split1(v.z, h[2], l[2]); split1(v.w, h[3], l[3]);
        *(ushort4*)&g_whi[base + k] = make_ushort4(h[0], h[1], h[2], h[3]);
        *(ushort4*)&g_wlo[base + k] = make_ushort4(l[0], l[1], l[2], l[3]);
    }
    if (threadIdx.x == 0) {
        const float* bx = (gate == 0) ? bx0 : (gate == 1) ? bx1 : (gate == 2) ? bx2 : bx3;
        const float* bh = (gate == 0) ? bh0 : (gate == 1) ? bh1 : (gate == 2) ? bh2 : bh3;
        g_bias[gidx] = bx[r] + bh[r];
    }
}

// =====================================================================
// Phase 1: tensor-core GEMM  xpT[t][g][b] = x @ Wx^T + bias
// M=65536, N=2048, K=512.  CTA tile 128m x 128n x 16k, double-buffered.
// 8 warps = 2 m x 4 n; warp tile 64x32; z = xh*wh + xl*wh + xh*wl.
// =====================================================================
__global__ __launch_bounds__(256, 2) void xp_mma() {
    __shared__ unsigned short As[2][2][128 * BKS];   // [buf][hi/lo][row*24+k]
    __shared__ unsigned short Bs[2][2][128 * BKS];

    const int tid = threadIdx.x;
    const int bn  = blockIdx.x;            // 0..15
    const int bm  = blockIdx.y;            // 0..511
    const int row0 = bm * 128;
    const int col0 = bn * 128;

    const int ln  = tid & 31, w = tid >> 5;
    const int wm  = w & 1;                 // m warp (64 rows)
    const int wn  = w >> 1;                // n warp (32 cols)
    const int gid = ln >> 2, tig = ln & 3;

    // staging indices: 512 16B-chunks each for A and B, 2 per thread each
    // idx: plane = idx>>8, row = (idx&255)>>1, chunk = idx&1
    auto stage = [&](int buf, int ks) {
        #pragma unroll
        for (int i = 0; i < 2; i++) {
            int idx = tid + i * 256;
            int pl = idx >> 8, row = (idx & 255) >> 1, ch = idx & 1;
            unsigned dst = smem_u32(&As[buf][pl][row * BKS]) + (unsigned)(ch * 16);
            const unsigned short* src = (pl ? g_xlo : g_xhi)
                + (size_t)(row0 + row) * IN_SZ + ks * 16 + ch * 8;
            cp_async16(dst, src);
        }
        #pragma unroll
        for (int i = 0; i < 2; i++) {
            int idx = tid + i * 256;
            int pl = idx >> 8, row = (idx & 255) >> 1, ch = idx & 1;
            unsigned dst = smem_u32(&Bs[buf][pl][row * BKS]) + (unsigned)(ch * 16);
            const unsigned short* src = (pl ? g_wlo : g_whi)
                + (size_t)(col0 + row) * IN_SZ + ks * 16 + ch * 8;
            cp_async16(dst, src);
        }
    };

    float acc[4][4][4];
    #pragma unroll
    for (int mf = 0; mf < 4; mf++)
        #pragma unroll
        for (int nf = 0; nf < 4; nf++)
            #pragma unroll
            for (int q = 0; q < 4; q++) acc[mf][nf][q] = 0.0f;

    stage(0, 0);
    cp_commit();

    const int NK = IN_SZ / 16;   // 32
    for (int ks = 0; ks < NK; ks++) {
        if (ks + 1 < NK) { stage((ks + 1) & 1, ks + 1); cp_commit(); cp_wait_n(1); }
        else             { cp_wait_n(0); }
        __syncthreads();

        const int buf = ks & 1;
        // A fragments (hi & lo), 4 m-frags
        unsigned a_hi[4][4], a_lo[4][4];
        #pragma unroll
        for (int mf = 0; mf < 4; mf++) {
            int r0 = (wm * 64 + mf * 16 + gid) * BKS + 2 * tig;
            int r8 = r0 + 8 * BKS;
            a_hi[mf][0] = *(const unsigned*)&As[buf][0][r0];
            a_hi[mf][1] = *(const unsigned*)&As[buf][0][r8];
            a_hi[mf][2] = *(const unsigned*)&As[buf][0][r0 + 8];
            a_hi[mf][3] = *(const unsigned*)&As[buf][0][r8 + 8];
            a_lo[mf][0] = *(const unsigned*)&As[buf][1][r0];
            a_lo[mf][1] = *(const unsigned*)&As[buf][1][r8];
            a_lo[mf][2] = *(const unsigned*)&As[buf][1][r0 + 8];
            a_lo[mf][3] = *(const unsigned*)&As[buf][1][r8 + 8];
        }
        #pragma unroll
        for (int nf = 0; nf < 4; nf++) {
            int r = (wn * 32 + nf * 8 + gid) * BKS + 2 * tig;
            unsigned bh0 = *(const unsigned*)&Bs[buf][0][r];
            unsigned bh1 = *(const unsigned*)&Bs[buf][0][r + 8];
            unsigned bl0 = *(const unsigned*)&Bs[buf][1][r];
            unsigned bl1 = *(const unsigned*)&Bs[buf][1][r + 8];
            #pragma unroll
            for (int mf = 0; mf < 4; mf++) {
                mma16816(acc[mf][nf], a_hi[mf], bh0, bh1);
                mma16816(acc[mf][nf], a_lo[mf], bh0, bh1);
                mma16816(acc[mf][nf], a_hi[mf], bl0, bl1);
            }
        }
        __syncthreads();
    }

    // epilogue: bias + store to g_xpT[t][g][b]
    #pragma unroll
    for (int nf = 0; nf < 4; nf++) {
        int n0 = col0 + wn * 32 + nf * 8 + 2 * tig;
        float bz0 = g_bias[n0], bz1 = g_bias[n0 + 1];
        #pragma unroll
        for (int mf = 0; mf < 4; mf++) {
            int m0 = row0 + wm * 64 + mf * 16 + gid;     // (m0&63) <= 55, +8 same t
            size_t t0 = (size_t)(m0 >> 6);
            int b0 = m0 & 63;
            size_t base = (t0 * G4 + n0) * B_SZ + b0;
            g_xpT[base]          = acc[mf][nf][0] + bz0;
            g_xpT[base + B_SZ]   = acc[mf][nf][1] + bz1;
            g_xpT[base + 8]      = acc[mf][nf][2] + bz0;
            g_xpT[base + B_SZ+8] = acc[mf][nf][3] + bz1;
        }
    }
}

// =====================================================================
// Phase 2: persistent recurrence (unchanged from R8 — passing, 3.9 ms).
// =====================================================================
__global__ __launch_bounds__(512, 1) void lstm_rec(
    const float* __restrict__ Whf, const float* __restrict__ Whi,
    const float* __restrict__ Who, const float* __restrict__ Whg,
    float* __restrict__ out)
{
    __shared__ unsigned short hsA[2][BPS * HSP];
    __shared__ unsigned short hsB[2][BPS * HSP];
    __shared__ float zpart[4][64][8];

    const int tid = threadIdx.x;
    const int ct  = blockIdx.x;
    const int cw  = ct & 31;
    const int sA  = (ct >> 5) * 2;
    const int sB  = sA + 1;
    const int j0  = cw * UPC;
    const int B0A = sA * BPS;
    const int B0B = sB * BPS;

    const int w   = tid >> 5;
    const int mt  = w & 3;
    const int kw  = w >> 2;
    const int ln  = tid & 31;
    const int g   = ln >> 2;
    const int t2  = ln & 3;

    const float* whp = (mt == 0) ? Whf : (mt == 1) ? Whi : (mt == 2) ? Who : Whg;
    unsigned a_hi[8][4], a_lo[8][4];
    {
        const float* Wr  = whp + (size_t)(j0 + g) * H_SZ;
        const float* Wr8 = whp + (size_t)(j0 + g + 8) * H_SZ;
        #pragma unroll
        for (int kt = 0; kt < 8; kt++) {
            int kb = kw * 128 + kt * 16 + 2 * t2;
            split2(*(const float2*)&Wr [kb],     a_hi[kt][0], a_lo[kt][0]);
            split2(*(const float2*)&Wr8[kb],     a_hi[kt][1], a_lo[kt][1]);
            split2(*(const float2*)&Wr [kb + 8], a_hi[kt][2], a_lo[kt][2]);
            split2(*(const float2*)&Wr8[kb + 8], a_hi[kt][3], a_lo[kt][3]);
        }
    }

    const unsigned baseA = flag_acquire(&g_arrive[sA * CPS + cw]);
    const unsigned baseB = flag_acquire(&g_arrive[sB * CPS + cw]);
    __syncthreads();

    const int ul = tid >> 3;
    const int ub = tid & 7;
    float cA = 0.0f, cB = 0.0f;

    for (int t = 0; t < T_STEPS; t++) {
        float xqA[4], xqB[4];
        if (tid < 128) {
            size_t xb = ((size_t)t * G4 + j0 + ul) * B_SZ;
            #pragma unroll
            for (int q = 0; q < 4; q++) {
                xqA[q] = g_xpT[xb + (size_t)q * 512 * B_SZ + B0A + ub];
                xqB[q] = g_xpT[xb + (size_t)q * 512 * B_SZ + B0B + ub];
            }
        }

        #pragma unroll
        for (int half = 0; half < 2; half++) {
            const int       s    = half ? sB : sA;
            unsigned short (*hs)[BPS * HSP] = half ? hsB : hsA;
            const unsigned  base = half ? baseB : baseA;
            const int       B0   = half ? B0B : B0A;
            float&          c    = half ? cB : cA;
            const float*    xq   = half ? xqB : xqA;

            if (t > 0) {
                if (tid < CPS) {
                    const unsigned* fp = &g_arrive[s * CPS + tid];
                    unsigned target = base + (unsigned)t;
                    while ((int)(flag_acquire(fp) - target) < 0) { }
                }
                __syncthreads();

                {
                    const size_t srcb = (((size_t)(t - 1) * NSTR + s) * BPS) * H_SZ;
                    const unsigned d_hi = smem_u32(&hs[0][0]);
                    const unsigned d_lo = smem_u32(&hs[1][0]);
                    #pragma unroll
                    for (int i = 0; i < 2; i++) {
                        int idx = tid + i * 512;
                        int pl = idx >> 9;
                        int b  = (idx >> 6) & 7;
                        int c8 = idx & 63;
                        unsigned dst = (pl ? d_lo : d_hi) + (unsigned)(b * HSP + c8 * 8) * 2;
                        const unsigned short* src = (pl ? g_hlo : g_hhi)
                                                    + srcb + (size_t)b * H_SZ + c8 * 8;
                        cp_async16(dst, src);
                    }
                }
                cp_commit_wait();
                __syncthreads();

                float d[4] = {0.f, 0.f, 0.f, 0.f};
                const unsigned short* hrow_hi = &hs[0][g * HSP];
                const unsigned short* hrow_lo = &hs[1][g * HSP];
                #pragma unroll
                for (int kt = 0; kt < 8; kt++) {
                    int kb = kw * 128 + kt * 16 + 2 * t2;
                    unsigned bh0 = *(const unsigned*)&hrow_hi[kb];
                    unsigned bh1 = *(const unsigned*)&hrow_hi[kb + 8];
                    unsigned bl0 = *(const unsigned*)&hrow_lo[kb];
                    unsigned bl1 = *(const unsigned*)&hrow_lo[kb + 8];
                    mma16816(d, a_hi[kt], bh0, bh1);
                    mma16816(d, a_lo[kt], bh0, bh1);
                    mma16816(d, a_hi[kt], bl0, bl1);
                }

                *(float2*)&zpart[kw][16 * mt + g][2 * t2]     = make_float2(d[0], d[1]);
                *(float2*)&zpart[kw][16 * mt + g + 8][2 * t2] = make_float2(d[2], d[3]);
            }
            __syncthreads();

            if (tid < 128) {
                float z[4];
                #pragma unroll
                for (int q = 0; q < 4; q++) {
                    float v = xq[q];
                    if (t > 0) {
                        #pragma unroll
                        for (int k4 = 0; k4 < 4; k4++)
                            v += zpart[k4][16 * q + ul][ub];
                    }
                    z[q] = v;
                }
                float f  = sig_apx(z[0]);
                float ii = sig_apx(z[1]);
                float o  = sig_apx(z[2]);
                float gg = tanh_apx(z[3]);
                c        = fmaf(f, c, ii * gg);
                float h  = o * tanh_apx(c);
                int j = j0 + ul;
                int B = B0 + ub;
                out[((size_t)t * B_SZ + B) * H_SZ + j] = h;
                unsigned short hh, hl;
                split1(h, hh, hl);
                size_t hb = (((size_t)t * NSTR + s) * BPS + ub) * H_SZ + j;
                g_hhi[hb] = hh;
                g_hlo[hb] = hl;
                if (t == T_STEPS - 1) {
                    size_t tail = (size_t)T_STEPS * B_SZ * H_SZ;
                    out[tail + (size_t)B * H_SZ + j] = h;
                    out[tail + (size_t)B_SZ * H_SZ + (size_t)B * H_SZ + j] = c;
                }
            }
            __syncthreads();
            if (tid == 0)
                flag_release(&g_arrive[s * CPS + cw], base + (unsigned)t + 1u);
        }
    }
}

// =====================================================================
extern "C" void kernel_launch(void* const* d_in, const int* in_sizes, int n_in,
                              void* d_out, int out_size)
{
    const float* x   = (const float*)d_in[0];
    const float* Wxf = (const float*)d_in[1];  const float* bxf = (const float*)d_in[2];
    const float* Whf = (const float*)d_in[3];  const float* bhf = (const float*)d_in[4];
    const float* Wxi = (const float*)d_in[5];  const float* bxi = (const float*)d_in[6];
    const float* Whi = (const float*)d_in[7];  const float* bhi = (const float*)d_in[8];
    const float* Wxo = (const float*)d_in[9];  const float* bxo = (const float*)d_in[10];
    const float* Who = (const float*)d_in[11]; const float* bho = (const float*)d_in[12];
    const float* Wxg = (const float*)d_in[13]; const float* bxg = (const float*)d_in[14];
    const float* Whg = (const float*)d_in[15]; const float* bhg = (const float*)d_in[16];
    float* out = (float*)d_out;

    // split inputs into bf16 hi/lo planes
    convert_x<<<(MROWS * IN_SZ) / (256 * 4), 256>>>(x);
    convert_w<<<G4, 128>>>(Wxf, Wxi, Wxo, Wxg,
                           bxf, bxi, bxo, bxg,
                           bhf, bhi, bho, bhg);

    // tensor-core input projection
    dim3 ggrid(G4 / 128, MROWS / 128);
    xp_mma<<<ggrid, 256>>>();

    // persistent recurrence
    lstm_rec<<<NCTA, 512>>>(Whf, Whi, Who, Whg, out);
}